// round 8
// baseline (speedup 1.0000x reference)
#include <cuda_runtime.h>
#include <cuda_bf16.h>
#include <math.h>

// Problem shape (fixed): B=64, T=1024, I=256, H=1024, P=10
// Output depends only on batch sample 63 (h[-1]); LSTM recurrence is
// independent per batch row, so we compute only sample 63's trajectory.
//
// Sync design: NO global barrier. Each h value is an 8-byte {tag=step, value}
// word published with st.relaxed.gpu.b64 and consumed by polling
// ld.relaxed.gpu.b64 (scoped => cannot be served stale indefinitely) until
// the tag matches. 8B relaxed atomicity makes tag+value indivisible; no
// fences needed. Buffers rotate over NBUF=4 slots; tag = step number.
//
// R8 delta vs the 1265us kernel: producer poll is two-slot pipelined (a
// second probe pair is always in flight), cutting detection lag from
// ~1.5x RTT to ~1x RTT. Loads stay ld.relaxed.gpu.b64 -- the weak .cg v2
// poll of R7 raced the scoped store and hung on HW.

#define T_STEPS 1024
#define IDIM    256
#define HDIM    1024
#define PDIM    10

#define REC_CTAS    128   // CTA c owns h-cols [8c, 8c+8) -> 32 gate columns
#define REC_THREADS 544   // warp 0 = reducer; warps 1..16 = GEMV producers
#define NBUF        4

typedef unsigned long long u64;

// Scratch (static device globals; no allocation allowed)
__device__ float g_xproj[T_STEPS * 4 * HDIM];  // [t][gate][h], bias folded
__device__ u64   g_hbuf[NBUF][HDIM];           // {tag<<32 | f32 bits(h)}

// ---------------------------------------------------------------------------
// PTX helpers
// ---------------------------------------------------------------------------
__device__ __forceinline__ u64 ld_relaxed_gpu(const u64* p) {
    u64 v;
    asm volatile("ld.relaxed.gpu.b64 %0, [%1];" : "=l"(v) : "l"(p) : "memory");
    return v;
}
__device__ __forceinline__ void st_relaxed_gpu(u64* p, u64 v) {
    asm volatile("st.relaxed.gpu.b64 [%0], %1;" :: "l"(p), "l"(v) : "memory");
}
__device__ __forceinline__ u64 ffma2(u64 a, u64 b, u64 c) {
    u64 d;
    asm("fma.rn.f32x2 %0, %1, %2, %3;" : "=l"(d) : "l"(a), "l"(b), "l"(c));
    return d;
}
__device__ __forceinline__ u64 pack2(float lo, float hi) {
    u64 d;
    asm("mov.b64 %0, {%1, %2};" : "=l"(d) : "f"(lo), "f"(hi));
    return d;
}
__device__ __forceinline__ float2 unpack2(u64 v) {
    float lo, hi;
    asm("mov.b64 {%0, %1}, %2;" : "=f"(lo), "=f"(hi) : "l"(v));
    return make_float2(lo, hi);
}
__device__ __forceinline__ void bar_sync_named(int id, int cnt) {
    asm volatile("bar.sync %0, %1;" :: "r"(id), "r"(cnt) : "memory");
}
__device__ __forceinline__ void bar_arrive_named(int id, int cnt) {
    asm volatile("bar.arrive %0, %1;" :: "r"(id), "r"(cnt) : "memory");
}
// tanh via MUFU: 1 - 2/(exp(2x)+1). Saturates correctly for |x| large.
__device__ __forceinline__ float fast_tanh(float x) {
    return 1.f - __fdividef(2.f, __expf(2.f * x) + 1.f);
}

// ---------------------------------------------------------------------------
// Kernel 1: x_proj[t][gate][h] = b_gate[h] + sum_i x[63,t,i] * Wgate_x[i,h]
// ---------------------------------------------------------------------------
__global__ __launch_bounds__(256) void xproj_kernel(
    const float* __restrict__ x,
    const float* __restrict__ Wfx, const float* __restrict__ bf,
    const float* __restrict__ Wix, const float* __restrict__ bi,
    const float* __restrict__ Wgx, const float* __restrict__ bg,
    const float* __restrict__ Wox, const float* __restrict__ bo)
{
    __shared__ float xs[32][IDIM];   // 32 KB

    const float* x63 = x + (size_t)63 * T_STEPS * IDIM;
    const int tid    = threadIdx.x;
    const int cc     = blockIdx.x;             // 0..15
    const int tchunk = blockIdx.y;             // 0..31
    const int gate   = cc >> 2;                // f=0, i=1, g=2, o=3
    const int col    = ((cc & 3) << 8) + tid;  // h-column within gate

    const float* W;
    const float* b;
    if      (gate == 0) { W = Wfx; b = bf; }
    else if (gate == 1) { W = Wix; b = bi; }
    else if (gate == 2) { W = Wgx; b = bg; }
    else                { W = Wox; b = bo; }

    #pragma unroll 4
    for (int k = 0; k < 32; k++)
        xs[k][tid] = x63[(size_t)(tchunk * 32 + k) * IDIM + tid];
    __syncthreads();

    float acc[32];
    #pragma unroll
    for (int t = 0; t < 32; t++) acc[t] = 0.f;

    for (int i = 0; i < IDIM; i++) {
        float wv = __ldg(&W[(size_t)i * HDIM + col]);
        #pragma unroll
        for (int t = 0; t < 32; t++)
            acc[t] = fmaf(xs[t][i], wv, acc[t]);
    }

    const float bias = __ldg(&b[col]);
    #pragma unroll
    for (int t = 0; t < 32; t++)
        g_xproj[(size_t)(tchunk * 32 + t) * 4096 + gate * HDIM + col] = acc[t] + bias;
}

// ---------------------------------------------------------------------------
// Kernel 2: persistent recurrence, 1024 steps, tag-polling synchronization.
// Warps 1..16: warp w consumes h rows [64(w-1), 64w): two-slot pipelined
//   tag-poll (relaxed scoped loads), smem stage, 32 packed f32x2 FMAs
//   against register-resident weight pairs, one partial, bar.arrive.
// Warp 0: prefetches xproj (hidden under bar wait), bar.sync, treed 16->1
//   reduce, sigmoid gates, cell update + fast tanh, publishes 8 tagged h.
// partial[] is single-buffered: producers cannot write step-(t+1) partials
// until warp 0 published h(t+1), which follows its step-t reduce.
// ---------------------------------------------------------------------------
__global__ __launch_bounds__(REC_THREADS, 1) void rec_kernel(
    const float* __restrict__ Wfh, const float* __restrict__ Wih,
    const float* __restrict__ Wgh, const float* __restrict__ Woh,
    const float* __restrict__ Wph, const float* __restrict__ bp,
    float* __restrict__ out)
{
    __shared__ __align__(16) float hs[16][64];   // per-producer-warp h slice
    __shared__ float partial[16][33];            // [producer][gate-col]

    const int tid  = threadIdx.x;
    const int w    = tid >> 5;
    const int lane = tid & 31;
    const int c    = blockIdx.x;

    const int gate = lane >> 3;
    const int hh   = lane & 7;
    const int hcol = c * 8 + hh;

    if (w == 0) {
        // ---------------- Reducer warp ----------------
        float Creg = 0.f;  // lanes 0..7 hold C for h-cols [8c, 8c+8)
        const float* xpp = &g_xproj[(size_t)gate * HDIM + hcol];

        for (int t = 0; t < T_STEPS; t++) {
            const float xp = __ldg(xpp + (size_t)t * 4096);  // hidden by bar wait
            bar_sync_named(1 + (t & 1), REC_THREADS);

            // Treed 16 -> 1 reduction of producer partials
            float p0 = partial[ 0][lane], p1 = partial[ 1][lane];
            float p2 = partial[ 2][lane], p3 = partial[ 3][lane];
            float p4 = partial[ 4][lane], p5 = partial[ 5][lane];
            float p6 = partial[ 6][lane], p7 = partial[ 7][lane];
            float p8 = partial[ 8][lane], p9 = partial[ 9][lane];
            float pa = partial[10][lane], pb = partial[11][lane];
            float pc = partial[12][lane], pd = partial[13][lane];
            float pe = partial[14][lane], pf = partial[15][lane];
            float s = (((p0 + p1) + (p2 + p3)) + ((p4 + p5) + (p6 + p7)))
                    + (((p8 + p9) + (pa + pb)) + ((pc + pd) + (pe + pf)))
                    + xp;

            // All four gates are sigmoid (per reference)
            const float sg = __fdividef(1.f, 1.f + __expf(-s));
            const float iv = __shfl_sync(0xffffffffu, sg,  8 + hh);
            const float gv = __shfl_sync(0xffffffffu, sg, 16 + hh);
            const float ov = __shfl_sync(0xffffffffu, sg, 24 + hh);
            if (lane < 8) {
                Creg = fmaf(Creg, sg, gv * iv);          // C = C*f + g*i
                const float hn = ov * fast_tanh(Creg);   // h = o*tanh(C)
                const u64 pk = ((u64)(unsigned)(t + 1) << 32)
                             | (u64)__float_as_uint(hn);
                st_relaxed_gpu(&g_hbuf[(t + 1) & (NBUF - 1)][hcol], pk);
            }
        }
    } else {
        // ---------------- Producer warps 1..16 ----------------
        const int pw = w - 1;                 // producer index 0..15
        const float* Wp = (gate == 0) ? Wfh : (gate == 1) ? Wih
                        : (gate == 2) ? Wgh : Woh;

        // Register-resident weight pairs for rows [64*pw, 64*pw+64)
        u64 W2[32];
        {
            const float* base = Wp + (size_t)(pw * 64) * HDIM + hcol;
            #pragma unroll
            for (int j = 0; j < 32; j++)
                W2[j] = pack2(base[(size_t)(2 * j) * HDIM],
                              base[(size_t)(2 * j + 1) * HDIM]);
        }

        const int e = pw * 64 + 2 * lane;     // this lane's two h indices

        for (int t = 0; t < T_STEPS; t++) {
            // Two-slot pipelined poll: a second probe pair is always in
            // flight while the previous pair is tested, so detection lag
            // is ~one RTT instead of up to two.
            const u64* hin = g_hbuf[t & (NBUF - 1)];
            const unsigned tg = (unsigned)t;
            u64 v0 = ld_relaxed_gpu(&hin[e]);
            u64 v1 = ld_relaxed_gpu(&hin[e + 1]);
            u64 y0 = ld_relaxed_gpu(&hin[e]);
            u64 y1 = ld_relaxed_gpu(&hin[e + 1]);
            while ((unsigned)(v0 >> 32) != tg || (unsigned)(v1 >> 32) != tg) {
                v0 = y0; v1 = y1;
                y0 = ld_relaxed_gpu(&hin[e]);
                y1 = ld_relaxed_gpu(&hin[e + 1]);
            }
            hs[pw][2 * lane]     = __uint_as_float((unsigned)v0);
            hs[pw][2 * lane + 1] = __uint_as_float((unsigned)v1);
            __syncwarp();

            // GEMV partial: 64 rows x 1 gate-column, packed f32x2
            const ulonglong2* hp = reinterpret_cast<const ulonglong2*>(hs[pw]);
            u64 acc0 = 0, acc1 = 0, acc2 = 0, acc3 = 0;  // {0.f, 0.f} bits
            #pragma unroll
            for (int k = 0; k < 8; k++) {
                ulonglong2 ha = hp[2 * k];
                ulonglong2 hb = hp[2 * k + 1];
                acc0 = ffma2(W2[4 * k + 0], ha.x, acc0);
                acc1 = ffma2(W2[4 * k + 1], ha.y, acc1);
                acc2 = ffma2(W2[4 * k + 2], hb.x, acc2);
                acc3 = ffma2(W2[4 * k + 3], hb.y, acc3);
            }
            float2 f0 = unpack2(acc0), f1 = unpack2(acc1);
            float2 f2 = unpack2(acc2), f3 = unpack2(acc3);
            partial[pw][lane] =
                ((f0.x + f0.y) + (f1.x + f1.y)) + ((f2.x + f2.y) + (f3.x + f3.y));

            __threadfence_block();                       // order partial write
            bar_arrive_named(1 + (t & 1), REC_THREADS);  // non-blocking
        }
    }

    // Head: y[p] = bp[p] + sum_h h_final[h] * Wph[h][p]   (CTA 0 only)
    if (c == 0 && tid < 32 * PDIM) {
        const u64* hf = g_hbuf[T_STEPS & (NBUF - 1)];
        const int p = tid >> 5;
        float acc = 0.f;
        for (int k = lane; k < HDIM; k += 32) {
            u64 v = ld_relaxed_gpu(&hf[k]);
            while ((unsigned)(v >> 32) != (unsigned)T_STEPS)
                v = ld_relaxed_gpu(&hf[k]);
            acc = fmaf(__uint_as_float((unsigned)v),
                       __ldg(&Wph[(size_t)k * PDIM + p]), acc);
        }
        #pragma unroll
        for (int off = 16; off; off >>= 1)
            acc += __shfl_down_sync(0xffffffffu, acc, off);
        if (lane == 0) out[p] = acc + __ldg(&bp[p]);
    }
}

// ---------------------------------------------------------------------------
extern "C" void kernel_launch(void* const* d_in, const int* in_sizes, int n_in,
                              void* d_out, int out_size)
{
    const float* x   = (const float*)d_in[0];
    const float* Wfx = (const float*)d_in[1];
    const float* Wfh = (const float*)d_in[2];
    const float* bf  = (const float*)d_in[3];
    const float* Wix = (const float*)d_in[4];
    const float* Wih = (const float*)d_in[5];
    const float* bi  = (const float*)d_in[6];
    const float* Wgx = (const float*)d_in[7];
    const float* Wgh = (const float*)d_in[8];
    const float* bg  = (const float*)d_in[9];
    const float* Wox = (const float*)d_in[10];
    const float* Woh = (const float*)d_in[11];
    const float* bo  = (const float*)d_in[12];
    const float* Wph = (const float*)d_in[13];
    const float* bp  = (const float*)d_in[14];
    float* out = (float*)d_out;

    // Tag 0 == "h^0 ready, value 0" -- zeroing IS the initial state.
    void* d_h = nullptr;
    cudaGetSymbolAddress(&d_h, g_hbuf);
    cudaMemsetAsync(d_h, 0, NBUF * HDIM * sizeof(u64));

    xproj_kernel<<<dim3(16, 32), 256>>>(x, Wfx, bf, Wix, bi, Wgx, bg, Wox, bo);
    rec_kernel<<<REC_CTAS, REC_THREADS>>>(Wfh, Wih, Wgh, Woh, Wph, bp, out);
}

// round 9
// speedup vs baseline: 1.5880x; 1.5880x over previous
#include <cuda_runtime.h>
#include <cuda_bf16.h>
#include <math.h>

// Problem shape (fixed): B=64, T=1024, I=256, H=1024, P=10
// Output depends only on batch sample 63 (h[-1]); LSTM recurrence is
// independent per batch row, so we compute only sample 63's trajectory.
//
// Sync design: NO global barrier. Each h value is an 8-byte {tag=step, value}
// word published with st.relaxed.gpu.b64 and consumed by polling
// ld.relaxed.gpu.b64 until the tag matches. 8B relaxed atomicity makes
// tag+value indivisible; no fences needed. Buffers rotate over NBUF=4 slots.
//
// R9 delta vs the 1265us kernel (R6): the producer poll uses UNIT lane
// stride (lane l polls words base+l and base+32+l) so each poll LDG
// coalesces 4 lanes per 32B sector -> 16 sector-reads per warp-iteration
// instead of 32. R8 proved the poll is L2-contention-bound (doubling poll
// traffic regressed 47%); this halves it instead.

#define T_STEPS 1024
#define IDIM    256
#define HDIM    1024
#define PDIM    10

#define REC_CTAS    128   // CTA c owns h-cols [8c, 8c+8) -> 32 gate columns
#define REC_THREADS 544   // warp 0 = reducer; warps 1..16 = GEMV producers
#define NBUF        4

typedef unsigned long long u64;

// Scratch (static device globals; no allocation allowed)
__device__ float g_xproj[T_STEPS * 4 * HDIM];            // [t][gate][h], bias folded
__device__ __align__(256) u64 g_hbuf[NBUF][HDIM];        // {tag<<32 | f32 bits(h)}

// ---------------------------------------------------------------------------
// PTX helpers
// ---------------------------------------------------------------------------
__device__ __forceinline__ u64 ld_relaxed_gpu(const u64* p) {
    u64 v;
    asm volatile("ld.relaxed.gpu.b64 %0, [%1];" : "=l"(v) : "l"(p) : "memory");
    return v;
}
__device__ __forceinline__ void st_relaxed_gpu(u64* p, u64 v) {
    asm volatile("st.relaxed.gpu.b64 [%0], %1;" :: "l"(p), "l"(v) : "memory");
}
__device__ __forceinline__ u64 ffma2(u64 a, u64 b, u64 c) {
    u64 d;
    asm("fma.rn.f32x2 %0, %1, %2, %3;" : "=l"(d) : "l"(a), "l"(b), "l"(c));
    return d;
}
__device__ __forceinline__ u64 pack2(float lo, float hi) {
    u64 d;
    asm("mov.b64 %0, {%1, %2};" : "=l"(d) : "f"(lo), "f"(hi));
    return d;
}
__device__ __forceinline__ float2 unpack2(u64 v) {
    float lo, hi;
    asm("mov.b64 {%0, %1}, %2;" : "=f"(lo), "=f"(hi) : "l"(v));
    return make_float2(lo, hi);
}
__device__ __forceinline__ void bar_sync_named(int id, int cnt) {
    asm volatile("bar.sync %0, %1;" :: "r"(id), "r"(cnt) : "memory");
}
__device__ __forceinline__ void bar_arrive_named(int id, int cnt) {
    asm volatile("bar.arrive %0, %1;" :: "r"(id), "r"(cnt) : "memory");
}
// tanh via MUFU: 1 - 2/(exp(2x)+1). Saturates correctly for |x| large.
__device__ __forceinline__ float fast_tanh(float x) {
    return 1.f - __fdividef(2.f, __expf(2.f * x) + 1.f);
}

// ---------------------------------------------------------------------------
// Kernel 1: x_proj[t][gate][h] = b_gate[h] + sum_i x[63,t,i] * Wgate_x[i,h]
// ---------------------------------------------------------------------------
__global__ __launch_bounds__(256) void xproj_kernel(
    const float* __restrict__ x,
    const float* __restrict__ Wfx, const float* __restrict__ bf,
    const float* __restrict__ Wix, const float* __restrict__ bi,
    const float* __restrict__ Wgx, const float* __restrict__ bg,
    const float* __restrict__ Wox, const float* __restrict__ bo)
{
    __shared__ float xs[32][IDIM];   // 32 KB

    const float* x63 = x + (size_t)63 * T_STEPS * IDIM;
    const int tid    = threadIdx.x;
    const int cc     = blockIdx.x;             // 0..15
    const int tchunk = blockIdx.y;             // 0..31
    const int gate   = cc >> 2;                // f=0, i=1, g=2, o=3
    const int col    = ((cc & 3) << 8) + tid;  // h-column within gate

    const float* W;
    const float* b;
    if      (gate == 0) { W = Wfx; b = bf; }
    else if (gate == 1) { W = Wix; b = bi; }
    else if (gate == 2) { W = Wgx; b = bg; }
    else                { W = Wox; b = bo; }

    #pragma unroll 4
    for (int k = 0; k < 32; k++)
        xs[k][tid] = x63[(size_t)(tchunk * 32 + k) * IDIM + tid];
    __syncthreads();

    float acc[32];
    #pragma unroll
    for (int t = 0; t < 32; t++) acc[t] = 0.f;

    for (int i = 0; i < IDIM; i++) {
        float wv = __ldg(&W[(size_t)i * HDIM + col]);
        #pragma unroll
        for (int t = 0; t < 32; t++)
            acc[t] = fmaf(xs[t][i], wv, acc[t]);
    }

    const float bias = __ldg(&b[col]);
    #pragma unroll
    for (int t = 0; t < 32; t++)
        g_xproj[(size_t)(tchunk * 32 + t) * 4096 + gate * HDIM + col] = acc[t] + bias;
}

// ---------------------------------------------------------------------------
// Kernel 2: persistent recurrence, 1024 steps, tag-polling synchronization.
// Warps 1..16: warp w consumes h rows [64(w-1), 64w): unit-stride coalesced
//   tag-poll (2 LDGs cover 16 sectors), smem stage, 32 packed f32x2 FMAs
//   against register-resident weight pairs, one partial, bar.arrive.
// Warp 0: prefetches xproj (hidden under bar wait), bar.sync, treed 16->1
//   reduce, sigmoid gates, cell update + fast tanh, publishes 8 tagged h.
// partial[] is single-buffered: producers cannot write step-(t+1) partials
// until warp 0 published h(t+1), which follows its step-t reduce.
// ---------------------------------------------------------------------------
__global__ __launch_bounds__(REC_THREADS, 1) void rec_kernel(
    const float* __restrict__ Wfh, const float* __restrict__ Wih,
    const float* __restrict__ Wgh, const float* __restrict__ Woh,
    const float* __restrict__ Wph, const float* __restrict__ bp,
    float* __restrict__ out)
{
    __shared__ __align__(16) float hs[16][64];   // per-producer-warp h slice
    __shared__ float partial[16][33];            // [producer][gate-col]

    const int tid  = threadIdx.x;
    const int w    = tid >> 5;
    const int lane = tid & 31;
    const int c    = blockIdx.x;

    const int gate = lane >> 3;
    const int hh   = lane & 7;
    const int hcol = c * 8 + hh;

    if (w == 0) {
        // ---------------- Reducer warp ----------------
        float Creg = 0.f;  // lanes 0..7 hold C for h-cols [8c, 8c+8)
        const float* xpp = &g_xproj[(size_t)gate * HDIM + hcol];

        for (int t = 0; t < T_STEPS; t++) {
            const float xp = __ldg(xpp + (size_t)t * 4096);  // hidden by bar wait
            bar_sync_named(1 + (t & 1), REC_THREADS);

            // Treed 16 -> 1 reduction of producer partials
            float p0 = partial[ 0][lane], p1 = partial[ 1][lane];
            float p2 = partial[ 2][lane], p3 = partial[ 3][lane];
            float p4 = partial[ 4][lane], p5 = partial[ 5][lane];
            float p6 = partial[ 6][lane], p7 = partial[ 7][lane];
            float p8 = partial[ 8][lane], p9 = partial[ 9][lane];
            float pa = partial[10][lane], pb = partial[11][lane];
            float pc = partial[12][lane], pd = partial[13][lane];
            float pe = partial[14][lane], pf = partial[15][lane];
            float s = (((p0 + p1) + (p2 + p3)) + ((p4 + p5) + (p6 + p7)))
                    + (((p8 + p9) + (pa + pb)) + ((pc + pd) + (pe + pf)))
                    + xp;

            // All four gates are sigmoid (per reference)
            const float sg = __fdividef(1.f, 1.f + __expf(-s));
            const float iv = __shfl_sync(0xffffffffu, sg,  8 + hh);
            const float gv = __shfl_sync(0xffffffffu, sg, 16 + hh);
            const float ov = __shfl_sync(0xffffffffu, sg, 24 + hh);
            if (lane < 8) {
                Creg = fmaf(Creg, sg, gv * iv);          // C = C*f + g*i
                const float hn = ov * fast_tanh(Creg);   // h = o*tanh(C)
                const u64 pk = ((u64)(unsigned)(t + 1) << 32)
                             | (u64)__float_as_uint(hn);
                st_relaxed_gpu(&g_hbuf[(t + 1) & (NBUF - 1)][hcol], pk);
            }
        }
    } else {
        // ---------------- Producer warps 1..16 ----------------
        const int pw = w - 1;                 // producer index 0..15
        const float* Wp = (gate == 0) ? Wfh : (gate == 1) ? Wih
                        : (gate == 2) ? Wgh : Woh;

        // Register-resident weight pairs for rows [64*pw, 64*pw+64)
        u64 W2[32];
        {
            const float* base = Wp + (size_t)(pw * 64) * HDIM + hcol;
            #pragma unroll
            for (int j = 0; j < 32; j++)
                W2[j] = pack2(base[(size_t)(2 * j) * HDIM],
                              base[(size_t)(2 * j + 1) * HDIM]);
        }

        const int base = pw * 64;             // this warp's h slice base

        for (int t = 0; t < T_STEPS; t++) {
            // Unit-stride coalesced poll: lane l polls words base+l and
            // base+32+l. Each LDG covers 32 consecutive 8B words = 8
            // sectors (4 lanes per 32B sector-read). Full 64-word probe =
            // 16 sector-reads per warp-iteration (the minimum).
            const u64* hin = g_hbuf[t & (NBUF - 1)] + base;
            const unsigned tg = (unsigned)t;
            u64 v0 = ld_relaxed_gpu(&hin[lane]);
            u64 v1 = ld_relaxed_gpu(&hin[lane + 32]);
            while ((unsigned)(v0 >> 32) != tg || (unsigned)(v1 >> 32) != tg) {
                v0 = ld_relaxed_gpu(&hin[lane]);
                v1 = ld_relaxed_gpu(&hin[lane + 32]);
            }
            hs[pw][lane]      = __uint_as_float((unsigned)v0);
            hs[pw][lane + 32] = __uint_as_float((unsigned)v1);
            __syncwarp();

            // GEMV partial: 64 rows x 1 gate-column, packed f32x2
            const ulonglong2* hp = reinterpret_cast<const ulonglong2*>(hs[pw]);
            u64 acc0 = 0, acc1 = 0, acc2 = 0, acc3 = 0;  // {0.f, 0.f} bits
            #pragma unroll
            for (int k = 0; k < 8; k++) {
                ulonglong2 ha = hp[2 * k];
                ulonglong2 hb = hp[2 * k + 1];
                acc0 = ffma2(W2[4 * k + 0], ha.x, acc0);
                acc1 = ffma2(W2[4 * k + 1], ha.y, acc1);
                acc2 = ffma2(W2[4 * k + 2], hb.x, acc2);
                acc3 = ffma2(W2[4 * k + 3], hb.y, acc3);
            }
            float2 f0 = unpack2(acc0), f1 = unpack2(acc1);
            float2 f2 = unpack2(acc2), f3 = unpack2(acc3);
            partial[pw][lane] =
                ((f0.x + f0.y) + (f1.x + f1.y)) + ((f2.x + f2.y) + (f3.x + f3.y));

            __threadfence_block();                       // order partial write
            bar_arrive_named(1 + (t & 1), REC_THREADS);  // non-blocking
        }
    }

    // Head: y[p] = bp[p] + sum_h h_final[h] * Wph[h][p]   (CTA 0 only)
    if (c == 0 && tid < 32 * PDIM) {
        const u64* hf = g_hbuf[T_STEPS & (NBUF - 1)];
        const int p = tid >> 5;
        float acc = 0.f;
        for (int k = lane; k < HDIM; k += 32) {
            u64 v = ld_relaxed_gpu(&hf[k]);
            while ((unsigned)(v >> 32) != (unsigned)T_STEPS)
                v = ld_relaxed_gpu(&hf[k]);
            acc = fmaf(__uint_as_float((unsigned)v),
                       __ldg(&Wph[(size_t)k * PDIM + p]), acc);
        }
        #pragma unroll
        for (int off = 16; off; off >>= 1)
            acc += __shfl_down_sync(0xffffffffu, acc, off);
        if (lane == 0) out[p] = acc + __ldg(&bp[p]);
    }
}

// ---------------------------------------------------------------------------
extern "C" void kernel_launch(void* const* d_in, const int* in_sizes, int n_in,
                              void* d_out, int out_size)
{
    const float* x   = (const float*)d_in[0];
    const float* Wfx = (const float*)d_in[1];
    const float* Wfh = (const float*)d_in[2];
    const float* bf  = (const float*)d_in[3];
    const float* Wix = (const float*)d_in[4];
    const float* Wih = (const float*)d_in[5];
    const float* bi  = (const float*)d_in[6];
    const float* Wgx = (const float*)d_in[7];
    const float* Wgh = (const float*)d_in[8];
    const float* bg  = (const float*)d_in[9];
    const float* Wox = (const float*)d_in[10];
    const float* Woh = (const float*)d_in[11];
    const float* bo  = (const float*)d_in[12];
    const float* Wph = (const float*)d_in[13];
    const float* bp  = (const float*)d_in[14];
    float* out = (float*)d_out;

    // Tag 0 == "h^0 ready, value 0" -- zeroing IS the initial state.
    void* d_h = nullptr;
    cudaGetSymbolAddress(&d_h, g_hbuf);
    cudaMemsetAsync(d_h, 0, NBUF * HDIM * sizeof(u64));

    xproj_kernel<<<dim3(16, 32), 256>>>(x, Wfx, bf, Wix, bi, Wgx, bg, Wox, bo);
    rec_kernel<<<REC_CTAS, REC_THREADS>>>(Wfh, Wih, Wgh, Woh, Wph, bp, out);
}